// round 9
// baseline (speedup 1.0000x reference)
#include <cuda_runtime.h>
#include <cstdint>

#define BB 512
#define TT 512
#define HH 128
#define Z4 512           // 4*H
#define PROT_B 432       // batches with L2-protected w1e (432*256KB = 108 MB < 126 MB L2)

// ---------------- persistent device scratch ----------------
__device__ float g_w1e[(size_t)BB * TT * HH];   // 134 MB: enc @ W1

// ---------------- transcendentals (identical to validated math) ----------------
__device__ __forceinline__ float ex2f(float x) {
    float r; asm("ex2.approx.f32 %0, %1;" : "=f"(r) : "f"(x)); return r;
}
__device__ __forceinline__ float rcpf(float x) {
    float r; asm("rcp.approx.f32 %0, %1;" : "=f"(r) : "f"(x)); return r;
}
__device__ __forceinline__ float tanh_acc(float x) {
    float ax = fabsf(x);
    float e  = ex2f(ax * -2.8853900817779268f);
    float r  = rcpf(e + 1.0f);
    float t  = fmaf(-2.0f * e, r, 1.0f);
    return copysignf(t, x);
}
__device__ __forceinline__ float sigm_acc(float x) {
    float e = ex2f(x * -1.4426950408889634f);
    return rcpf(e + 1.0f);
}

// ---------------- cache-policy helpers (createpolicy + cache_hint form; sm_80+) ----------------
__device__ __forceinline__ unsigned long long mk_policy_el() {
    unsigned long long p;
    asm("createpolicy.fractional.L2::evict_last.b64 %0, 1.0;" : "=l"(p));
    return p;
}
__device__ __forceinline__ unsigned long long mk_policy_ef() {
    unsigned long long p;
    asm("createpolicy.fractional.L2::evict_first.b64 %0, 1.0;" : "=l"(p));
    return p;
}
__device__ __forceinline__ float4 ldg_pol4(const float* p, unsigned long long pol) {
    float4 v;
    asm("ld.global.nc.L2::cache_hint.v4.f32 {%0,%1,%2,%3}, [%4], %5;"
        : "=f"(v.x), "=f"(v.y), "=f"(v.z), "=f"(v.w) : "l"(p), "l"(pol));
    return v;
}
__device__ __forceinline__ float ldg_pol(const float* p, unsigned long long pol) {
    float v;
    asm("ld.global.nc.L2::cache_hint.f32 %0, [%1], %2;" : "=f"(v) : "l"(p), "l"(pol));
    return v;
}
__device__ __forceinline__ void st_cs(float* p, float v) {           // streaming store
    asm volatile("st.global.cs.f32 [%0], %1;" :: "l"(p), "f"(v) : "memory");
}
#define BAR_SYNC(id, n)   asm volatile("bar.sync %0, %1;"   :: "r"(id), "r"(n) : "memory")
#define BAR_ARRIVE(id, n) asm volatile("bar.arrive %0, %1;" :: "r"(id), "r"(n) : "memory")

// ---------------- w1e[b,t,k] = sum_h enc[b,t,h] * W1[h,k]  (unchanged, validated) ----------------
__global__ void __launch_bounds__(256) k_w1e(const float* __restrict__ enc,
                                             const float* __restrict__ W1) {
    __shared__ float es[32 * HH];
    const int row0 = blockIdx.x * 32;
    const int tid  = threadIdx.x;
    for (int i = tid; i < 32 * HH; i += 256) es[i] = enc[(size_t)row0 * HH + i];
    __syncthreads();
    const int col = tid & 127;
    const int rg  = tid >> 7;
    float acc[16];
#pragma unroll
    for (int i = 0; i < 16; i++) acc[i] = 0.f;
    for (int k = 0; k < HH; k++) {
        float w = __ldg(&W1[k * HH + col]);
#pragma unroll
        for (int i = 0; i < 16; i++)
            acc[i] = fmaf(es[(rg * 16 + i) * HH + k], w, acc[i]);
    }
#pragma unroll
    for (int i = 0; i < 16; i++)
        g_w1e[(size_t)(row0 + rg * 16 + i) * HH + col] = acc[i];
}

// ---------------- score loop body (identical math/order to validated kernel) ----------------
__device__ __forceinline__ void score_rows(const float* wb, const float4 whv, const float4 vv,
                                           int w, float* sc_s, unsigned long long* red_s,
                                           int lane, unsigned long long pol) {
    float bmax = -3.4e38f; int bj = 0;
    for (int j = w; j < TT; j += 8) {
        const float4 e = ldg_pol4(wb + (size_t)j * HH, pol);
        float p = vv.x * tanh_acc(e.x + whv.x);
        p = fmaf(vv.y, tanh_acc(e.y + whv.y), p);
        p = fmaf(vv.z, tanh_acc(e.z + whv.z), p);
        p = fmaf(vv.w, tanh_acc(e.w + whv.w), p);
#pragma unroll
        for (int o = 16; o; o >>= 1) p += __shfl_xor_sync(0xffffffffu, p, o);
        if (lane == 0) {
            sc_s[j] = p;
            if (p > bmax) { bmax = p; bj = j; }     // strict >: first index wins in-warp
        }
    }
    if (lane == 0) {
        unsigned u = __float_as_uint(bmax);
        u = (u & 0x80000000u) ? ~u : (u | 0x80000000u);              // order-preserving map
        atomicMax(red_s, ((unsigned long long)u << 32) | (unsigned)(~bj)); // min-j on ties
    }
}

// ---------------- persistent per-batch sequence kernel ----------------
// One CTA per batch. Warp specialization inside each step:
//   gates (threads 0-127) -> sync -> { w0-3: wh, then scores | w4-7: zh(s+1)=h2@R, then scores }
//   handoff of wh via named barrier 2 (producer-arrive / consumer-sync).
__global__ void __launch_bounds__(256, 4) k_seq(
    const float* __restrict__ x,    const float* __restrict__ Kw,
    const float* __restrict__ R,    const float* __restrict__ bias,
    const float* __restrict__ W2,   const float* __restrict__ Vw,
    const float* __restrict__ h0,   const float* __restrict__ c0,
    float* __restrict__ out)
{
    __shared__ __align__(16) float h_s[HH];
    __shared__ __align__(16) float wh_s[HH];
    __shared__ __align__(16) float zh_s[Z4];     // h@R partial (no ptr/bias terms)
    __shared__ __align__(16) float sc_s[TT];
    __shared__ unsigned long long red_s;
    __shared__ float ptr_s[2];

    const int b    = blockIdx.x;
    const int tid  = threadIdx.x;
    const int lane = tid & 31;
    const int w    = tid >> 5;

    const unsigned long long pol_el = mk_policy_el();
    const unsigned long long pol_w1e = (b < PROT_B) ? pol_el : mk_policy_ef();

    if (tid < HH) h_s[tid] = h0[b * HH + tid];
    float c_reg = (tid < HH) ? c0[b * HH + tid] : 0.f;
    if (tid == 0) { ptr_s[0] = 1.f; ptr_s[1] = 1.f; red_s = 0ull; }

    const float4 vv = __ldg(&((const float4*)Vw)[lane]);
    const float* wb = g_w1e + (size_t)b * TT * HH + lane * 4;
    const int zc = tid - 128;                    // zh column base for warps 4-7

    __syncthreads();

    // prologue: zh for step 0 from h0 (same code path as steady state)
    if (tid >= 128) {
        float a0 = 0.f, a1 = 0.f, a2 = 0.f, a3 = 0.f;
#pragma unroll 4
        for (int k = 0; k < HH; k++) {
            const float hk = h_s[k];
            const float* rk = R + (size_t)k * Z4 + zc;
            a0 = fmaf(hk, ldg_pol(rk,       pol_el), a0);
            a1 = fmaf(hk, ldg_pol(rk + 128, pol_el), a1);
            a2 = fmaf(hk, ldg_pol(rk + 256, pol_el), a2);
            a3 = fmaf(hk, ldg_pol(rk + 384, pol_el), a3);
        }
        zh_s[zc] = a0; zh_s[zc + 128] = a1; zh_s[zc + 256] = a2; zh_s[zc + 384] = a3;
    }
    __syncthreads();

    for (int s = 0; s < TT; s++) {
        // ---- gates: z = ptr@K + zh + bias per column; Keras order i,f,g,o ----
        if (tid < HH) {
            const float px = ptr_s[0], py = ptr_s[1];
            const float zi = fmaf(py, __ldg(&Kw[Z4 + tid]),        px * __ldg(&Kw[tid]))
                             + zh_s[tid]        + __ldg(&bias[tid]);
            const float zf = fmaf(py, __ldg(&Kw[Z4 + HH + tid]),   px * __ldg(&Kw[HH + tid]))
                             + zh_s[HH + tid]   + __ldg(&bias[HH + tid]);
            const float zg = fmaf(py, __ldg(&Kw[Z4 + 2*HH + tid]), px * __ldg(&Kw[2*HH + tid]))
                             + zh_s[2*HH + tid] + __ldg(&bias[2*HH + tid]);
            const float zo = fmaf(py, __ldg(&Kw[Z4 + 3*HH + tid]), px * __ldg(&Kw[3*HH + tid]))
                             + zh_s[3*HH + tid] + __ldg(&bias[3*HH + tid]);
            const float c2 = fmaf(sigm_acc(zf), c_reg, sigm_acc(zi) * tanh_acc(zg));
            c_reg = c2;
            h_s[tid] = sigm_acc(zo) * tanh_acc(c2);
        }
        __syncthreads();

        if (tid < 128) {
            // ---- wh = h2 @ W2 (identical serial chain to validated kernel) ----
            float a = 0.f;
            for (int k = 0; k < HH; k++)
                a = fmaf(h_s[k], ldg_pol(&W2[k * HH + tid], pol_el), a);
            wh_s[tid] = a;
            BAR_SYNC(1, 128);       // wh visible among warps 0-3
            BAR_ARRIVE(2, 256);     // release warps 4-7
        } else {
            // ---- zh(s+1) = h2 @ R, overlapped with warps 0-3's wh + early scores ----
            float a0 = 0.f, a1 = 0.f, a2 = 0.f, a3 = 0.f;
#pragma unroll 4
            for (int k = 0; k < HH; k++) {
                const float hk = h_s[k];
                const float* rk = R + (size_t)k * Z4 + zc;
                a0 = fmaf(hk, ldg_pol(rk,       pol_el), a0);
                a1 = fmaf(hk, ldg_pol(rk + 128, pol_el), a1);
                a2 = fmaf(hk, ldg_pol(rk + 256, pol_el), a2);
                a3 = fmaf(hk, ldg_pol(rk + 384, pol_el), a3);
            }
            zh_s[zc] = a0; zh_s[zc + 128] = a1; zh_s[zc + 256] = a2; zh_s[zc + 384] = a3;
            BAR_SYNC(2, 256);       // wait for wh from warps 0-3
        }

        // ---- scores + argmax (identical per-row math, same 64-rows-per-warp partition) ----
        const float4 whv = ((const float4*)wh_s)[lane];
        score_rows(wb, whv, vv, w, sc_s, &red_s, lane, pol_w1e);
        __syncthreads();

        // ---- streaming output row + ptr feedback ----
        const size_t ofs = ((size_t)b * TT + s) * TT;
        st_cs(&out[ofs + tid],       sc_s[tid]);
        st_cs(&out[ofs + 256 + tid], sc_s[256 + tid]);
        if (tid == 0) {
            const unsigned j = ~(unsigned)(red_s & 0xffffffffu);
            ptr_s[0] = __ldg(&x[((size_t)b * TT + j) * 2 + 0]);
            ptr_s[1] = __ldg(&x[((size_t)b * TT + j) * 2 + 1]);
            red_s = 0ull;
        }
        __syncthreads();
    }
}

// ---------------- launch: 2-node graph ----------------
extern "C" void kernel_launch(void* const* d_in, const int* in_sizes, int n_in,
                              void* d_out, int out_size) {
    (void)in_sizes; (void)n_in; (void)out_size;
    const float* x    = (const float*)d_in[0];   // [512,512,2]
    const float* enc  = (const float*)d_in[1];   // [512,512,128]
    const float* h0   = (const float*)d_in[2];   // [512,128]
    const float* c0   = (const float*)d_in[3];   // [512,128]
    const float* Kw   = (const float*)d_in[4];   // [2,512]
    const float* R    = (const float*)d_in[5];   // [128,512]
    const float* bias = (const float*)d_in[6];   // [512]
    const float* W1   = (const float*)d_in[7];   // [128,128]
    const float* W2   = (const float*)d_in[8];   // [128,128]
    const float* Vw   = (const float*)d_in[9];   // [128,1]
    float* out = (float*)d_out;                  // [512,512,512]

    k_w1e<<<(BB * TT) / 32, 256>>>(enc, W1);
    k_seq<<<BB, 256>>>(x, Kw, R, bias, W2, Vw, h0, c0, out);
}